// round 15
// baseline (speedup 1.0000x reference)
#include <cuda_runtime.h>
#include <cuda_fp16.h>
#include <math.h>

#define N_NODES 50000
#define N_EDGES 800000
#define IN_DIM  128
#define HID_DIM 128
#define OUT_DIM 64

typedef unsigned long long ull;

// ---------------- scratch (static device globals; no allocation) ----------------
__device__ float  g_dinv[N_NODES];
__device__ int    g_degi[N_NODES];
__device__ int    g_off [N_NODES + 1];
__device__ int    g_cur [N_NODES];
__device__ int    g_bsum[256];
__device__ ull    g_edge[N_EDGES];                    // packed {dinv[src]:32 | src:32}
__device__ __half g_hh  [(size_t)N_NODES * HID_DIM];
__device__ __half g_h2h [(size_t)N_NODES * OUT_DIM];

// ---------------- f32x2 packed math ----------------
__device__ __forceinline__ ull pack2(float lo, float hi) {
    ull r; asm("mov.b64 %0, {%1, %2};" : "=l"(r) : "f"(lo), "f"(hi)); return r;
}
__device__ __forceinline__ ull fma2(ull a, ull b, ull c) {
    ull d; asm("fma.rn.f32x2 %0, %1, %2, %3;" : "=l"(d) : "l"(a), "l"(b), "l"(c)); return d;
}
__device__ __forceinline__ float2 unpack2(ull p) {
    float2 f; asm("mov.b64 {%0, %1}, %2;" : "=f"(f.x), "=f"(f.y) : "l"(p)); return f;
}

// ---------------- degree / norm / CSR build ----------------
__global__ void k_zero() {
    int i = blockIdx.x * blockDim.x + threadIdx.x;
    if (i < N_NODES) g_degi[i] = 0;
}
__global__ void k_count(const int* __restrict__ dst) {
    int e = blockIdx.x * blockDim.x + threadIdx.x;
    if (e < N_EDGES) atomicAdd(&g_degi[dst[e]], 1);
}
__global__ void k_scan1() {
    __shared__ int s[256];
    int i = blockIdx.x * 256 + threadIdx.x;
    int v = (i < N_NODES) ? g_degi[i] : 0;
    if (i < N_NODES) g_dinv[i] = rsqrtf((float)(v + 1));  // +1 self-loop
    s[threadIdx.x] = v;
    __syncthreads();
    for (int d = 1; d < 256; d <<= 1) {
        int t = (threadIdx.x >= d) ? s[threadIdx.x - d] : 0;
        __syncthreads();
        s[threadIdx.x] += t;
        __syncthreads();
    }
    if (i < N_NODES) g_off[i] = s[threadIdx.x] - v;
    if (threadIdx.x == 255) g_bsum[blockIdx.x] = s[255];
}
__global__ void k_scan2(int nblk) {
    __shared__ int s[256];
    int t = threadIdx.x;
    int v = (t < nblk) ? g_bsum[t] : 0;
    s[t] = v;
    __syncthreads();
    for (int d = 1; d < 256; d <<= 1) {
        int u = (t >= d) ? s[t - d] : 0;
        __syncthreads();
        s[t] += u;
        __syncthreads();
    }
    if (t < nblk) g_bsum[t] = s[t] - v;
}
__global__ void k_scan3() {
    int i = blockIdx.x * blockDim.x + threadIdx.x;
    if (i < N_NODES) {
        int o = g_off[i] + g_bsum[i >> 8];
        g_off[i] = o;
        g_cur[i] = o;
    }
    if (i == 0) g_off[N_NODES] = N_EDGES;
}
// fill packed edge records: {dinv[src] | src}. dinv ready (scan1 precedes).
__global__ void k_fill(const int* __restrict__ src, const int* __restrict__ dst) {
    int e = blockIdx.x * blockDim.x + threadIdx.x;
    if (e < N_EDGES) {
        int s = src[e];
        int p = atomicAdd(&g_cur[dst[e]], 1);
        g_edge[p] = ((ull)__float_as_uint(g_dinv[s]) << 32) | (unsigned)s;
    }
}

// ---------------- GEMM (R10-exact f32x2 microtile), fp16 output -----------------
template <int K, int N, int RB, int TY>
__global__ void k_gemm(const float* __restrict__ X, const float* __restrict__ W,
                       __half* __restrict__ Y) {
    constexpr int CP = N / 32;
    constexpr int T  = TY * 16;
    __shared__ float xs[RB * 33];
    __shared__ float ws[32 * N];
    const int tid = threadIdx.x;
    const int tx = tid & 15, ty = tid >> 4;
    const long r0 = (long)blockIdx.x * RB;

    ull acc[8][CP];
#pragma unroll
    for (int r = 0; r < 8; r++)
#pragma unroll
        for (int c = 0; c < CP; c++) acc[r][c] = 0ull;

    for (int k0 = 0; k0 < K; k0 += 32) {
        for (int t = tid; t < RB * 8; t += T) {
            int r = t >> 3, q = t & 7;
            long row = r0 + r; if (row >= N_NODES) row = N_NODES - 1;
            float4 v = __ldg((const float4*)(X + row * K + k0) + q);
            float* xp = &xs[r * 33 + q * 4];
            xp[0] = v.x; xp[1] = v.y; xp[2] = v.z; xp[3] = v.w;
        }
        const float4* wsrc = (const float4*)(W + (size_t)k0 * N);
        for (int t = tid; t < 8 * N; t += T)
            ((float4*)ws)[t] = __ldg(wsrc + t);
        __syncthreads();

#pragma unroll 8
        for (int kk = 0; kk < 32; kk++) {
            ull wv[CP];
#pragma unroll
            for (int c = 0; c < CP; c++)
                wv[c] = *(const ull*)&ws[kk * N + 2 * tx + 32 * c];
#pragma unroll
            for (int r = 0; r < 8; r++) {
                float xv = xs[(ty * 8 + r) * 33 + kk];
                ull xx = pack2(xv, xv);
#pragma unroll
                for (int c = 0; c < CP; c++) acc[r][c] = fma2(xx, wv[c], acc[r][c]);
            }
        }
        __syncthreads();
    }

#pragma unroll
    for (int r = 0; r < 8; r++) {
        long row = r0 + ty * 8 + r;
        if (row < N_NODES) {
#pragma unroll
            for (int c = 0; c < CP; c++) {
                float2 f = unpack2(acc[r][c]);
                *(__half2*)&Y[row * N + 2 * tx + 32 * c] = __floats2half2_rn(f.x, f.y);
            }
        }
    }
}

// ---------------- pull aggregation, C=128: packed edge recs, 2-way ---------------
__global__ void k_pull128(const __half* __restrict__ hraw, const float* __restrict__ b,
                          float* __restrict__ out) {
    int w = (blockIdx.x * blockDim.x + threadIdx.x) >> 5;
    if (w >= N_NODES) return;
    int lane = threadIdx.x & 31;
    float din = g_dinv[w];
    uint2 hr = __ldg((const uint2*)(hraw + (size_t)w * 128) + lane);
    float2 h0a = __half22float2(*(__half2*)&hr.x);
    float2 h0b = __half22float2(*(__half2*)&hr.y);
    float4 bv = __ldg((const float4*)b + lane);
    float sl = din * din;
    float4 acc, acc2 = make_float4(0.f, 0.f, 0.f, 0.f);
    acc.x = fmaf(h0a.x, sl, bv.x); acc.y = fmaf(h0a.y, sl, bv.y);
    acc.z = fmaf(h0b.x, sl, bv.z); acc.w = fmaf(h0b.y, sl, bv.w);

    int s0 = g_off[w], s1 = g_off[w + 1];
    for (int j0 = s0; j0 < s1; j0 += 32) {
        int jj = j0 + lane;
        ull ed = 0;
        if (jj < s1) ed = g_edge[jj];
        int cnt = min(32, s1 - j0);
        int i = 0;
        for (; i + 2 <= cnt; i += 2) {
            ull eA = __shfl_sync(0xffffffffu, ed, i);
            ull eB = __shfl_sync(0xffffffffu, ed, i + 1);
            int   sA = (int)(unsigned)eA;
            int   sB = (int)(unsigned)eB;
            float nA = __uint_as_float((unsigned)(eA >> 32)) * din;
            float nB = __uint_as_float((unsigned)(eB >> 32)) * din;
            uint2 rA = __ldg((const uint2*)(hraw + (size_t)sA * 128) + lane);
            uint2 rB = __ldg((const uint2*)(hraw + (size_t)sB * 128) + lane);
            float2 a0 = __half22float2(*(__half2*)&rA.x);
            float2 a1 = __half22float2(*(__half2*)&rA.y);
            float2 b0 = __half22float2(*(__half2*)&rB.x);
            float2 b1 = __half22float2(*(__half2*)&rB.y);
            acc.x  = fmaf(a0.x, nA, acc.x);  acc.y  = fmaf(a0.y, nA, acc.y);
            acc.z  = fmaf(a1.x, nA, acc.z);  acc.w  = fmaf(a1.y, nA, acc.w);
            acc2.x = fmaf(b0.x, nB, acc2.x); acc2.y = fmaf(b0.y, nB, acc2.y);
            acc2.z = fmaf(b1.x, nB, acc2.z); acc2.w = fmaf(b1.y, nB, acc2.w);
        }
        if (i < cnt) {
            ull eA = __shfl_sync(0xffffffffu, ed, i);
            int   sA = (int)(unsigned)eA;
            float nA = __uint_as_float((unsigned)(eA >> 32)) * din;
            uint2 rA = __ldg((const uint2*)(hraw + (size_t)sA * 128) + lane);
            float2 a0 = __half22float2(*(__half2*)&rA.x);
            float2 a1 = __half22float2(*(__half2*)&rA.y);
            acc.x = fmaf(a0.x, nA, acc.x); acc.y = fmaf(a0.y, nA, acc.y);
            acc.z = fmaf(a1.x, nA, acc.z); acc.w = fmaf(a1.y, nA, acc.w);
        }
    }
    acc.x = fmaxf(acc.x + acc2.x, 0.0f); acc.y = fmaxf(acc.y + acc2.y, 0.0f);
    acc.z = fmaxf(acc.z + acc2.z, 0.0f); acc.w = fmaxf(acc.w + acc2.w, 0.0f);
    ((float4*)(out + (size_t)w * 128))[lane] = acc;
}

// ---------------- pull aggregation, C=64: packed edge recs, 2-way ----------------
__global__ void k_pull64(const __half* __restrict__ hraw, const float* __restrict__ b,
                         float* __restrict__ out) {
    int w = (blockIdx.x * blockDim.x + threadIdx.x) >> 5;
    if (w >= N_NODES) return;
    int lane = threadIdx.x & 31;
    float din = g_dinv[w];
    unsigned hr = __ldg((const unsigned*)(hraw + (size_t)w * 64) + lane);
    float2 h0 = __half22float2(*(__half2*)&hr);
    float2 bv = __ldg((const float2*)b + lane);
    float sl = din * din;
    float2 acc, acc2 = make_float2(0.f, 0.f);
    acc.x = fmaf(h0.x, sl, bv.x); acc.y = fmaf(h0.y, sl, bv.y);

    int s0 = g_off[w], s1 = g_off[w + 1];
    for (int j0 = s0; j0 < s1; j0 += 32) {
        int jj = j0 + lane;
        ull ed = 0;
        if (jj < s1) ed = g_edge[jj];
        int cnt = min(32, s1 - j0);
        int i = 0;
        for (; i + 2 <= cnt; i += 2) {
            ull eA = __shfl_sync(0xffffffffu, ed, i);
            ull eB = __shfl_sync(0xffffffffu, ed, i + 1);
            int   sA = (int)(unsigned)eA;
            int   sB = (int)(unsigned)eB;
            float nA = __uint_as_float((unsigned)(eA >> 32)) * din;
            float nB = __uint_as_float((unsigned)(eB >> 32)) * din;
            unsigned rA = __ldg((const unsigned*)(hraw + (size_t)sA * 64) + lane);
            unsigned rB = __ldg((const unsigned*)(hraw + (size_t)sB * 64) + lane);
            float2 fA = __half22float2(*(__half2*)&rA);
            float2 fB = __half22float2(*(__half2*)&rB);
            acc.x  = fmaf(fA.x, nA, acc.x);  acc.y  = fmaf(fA.y, nA, acc.y);
            acc2.x = fmaf(fB.x, nB, acc2.x); acc2.y = fmaf(fB.y, nB, acc2.y);
        }
        if (i < cnt) {
            ull eA = __shfl_sync(0xffffffffu, ed, i);
            int   sA = (int)(unsigned)eA;
            float nA = __uint_as_float((unsigned)(eA >> 32)) * din;
            unsigned rA = __ldg((const unsigned*)(hraw + (size_t)sA * 64) + lane);
            float2 fA = __half22float2(*(__half2*)&rA);
            acc.x = fmaf(fA.x, nA, acc.x); acc.y = fmaf(fA.y, nA, acc.y);
        }
    }
    acc.x += acc2.x; acc.y += acc2.y;
    ((float2*)(out + (size_t)w * 64))[lane] = acc;
}

// ---------------- launch: R10 structure (CSR ∥ GEMM1) ----------------------------
extern "C" void kernel_launch(void* const* d_in, const int* in_sizes, int n_in,
                              void* d_out, int out_size) {
    const float* x  = (const float*)d_in[0];
    const int*   ei = (const int*)  d_in[1];
    const float* W1 = (const float*)d_in[2];
    const float* b1 = (const float*)d_in[3];
    const float* W2 = (const float*)d_in[4];
    const float* b2 = (const float*)d_in[5];

    const int* src = ei;
    const int* dst = ei + N_EDGES;

    float* out_h2 = (float*)d_out;                       // [N, 64]
    float* out_h1 = out_h2 + (size_t)N_NODES * OUT_DIM;  // [N, 128]

    void *p_hh, *p_h2h;
    cudaGetSymbolAddress(&p_hh,  g_hh);
    cudaGetSymbolAddress(&p_h2h, g_h2h);
    __half* hhbuf  = (__half*)p_hh;
    __half* h2hbuf = (__half*)p_h2h;

    static cudaStream_t s2 = nullptr;
    static cudaEvent_t  evFork = nullptr, evJoin = nullptr;
    if (s2 == nullptr) {
        cudaStreamCreateWithFlags(&s2, cudaStreamNonBlocking);
        cudaEventCreateWithFlags(&evFork, cudaEventDisableTiming);
        cudaEventCreateWithFlags(&evJoin, cudaEventDisableTiming);
    }

    const int TB = 256;
    const int nblk_nodes = (N_NODES + TB - 1) / TB;
    const int nblk_edges = (N_EDGES + TB - 1) / TB;

    cudaEventRecord(evFork, 0);
    cudaStreamWaitEvent(s2, evFork, 0);

    // --- stream 0: GEMM1 -> fp16 hbuf ---
    k_gemm<IN_DIM, HID_DIM, 128, 16><<<(N_NODES + 127) / 128, 256>>>(x, W1, hhbuf);

    // --- stream s2: degree + CSR build (dinv before fill; packed edge recs) ---
    k_zero <<<nblk_nodes, TB, 0, s2>>>();
    k_count<<<nblk_edges, TB, 0, s2>>>(dst);
    k_scan1<<<nblk_nodes, TB, 0, s2>>>();
    k_scan2<<<1,          TB, 0, s2>>>(nblk_nodes);
    k_scan3<<<nblk_nodes, TB, 0, s2>>>();
    k_fill <<<nblk_edges, TB, 0, s2>>>(src, dst);

    cudaEventRecord(evJoin, s2);
    cudaStreamWaitEvent(0, evJoin, 0);

    // --- stream 0: pull1 -> GEMM2 -> pull2 ---
    k_pull128<<<(N_NODES * 32 + TB - 1) / TB, TB>>>(hhbuf, b1, out_h1);
    k_gemm<HID_DIM, OUT_DIM, 128, 16><<<(N_NODES + 127) / 128, 256>>>(out_h1, W2, h2hbuf);
    k_pull64<<<(N_NODES * 32 + TB - 1) / TB, TB>>>(h2hbuf, b2, out_h2);
}

// round 16
// speedup vs baseline: 1.0346x; 1.0346x over previous
#include <cuda_runtime.h>
#include <cuda_fp16.h>
#include <math.h>

#define N_NODES 50000
#define N_EDGES 800000
#define IN_DIM  128
#define HID_DIM 128
#define OUT_DIM 64

typedef unsigned long long ull;

// ---------------- scratch (static device globals; no allocation) ----------------
// NOTE: device globals are zero-initialized at module load, so g_degi == 0 on the
// first call; k_scan3 re-zeroes it for every subsequent (graph-replayed) call.
__device__ float  g_dinv[N_NODES];
__device__ int    g_degi[N_NODES];
__device__ int    g_off [N_NODES + 1];
__device__ int    g_cur [N_NODES];
__device__ int    g_bsum[256];
__device__ int    g_col [N_EDGES];
__device__ __half g_hh  [(size_t)N_NODES * HID_DIM];
__device__ __half g_h2h [(size_t)N_NODES * OUT_DIM];

// ---------------- f32x2 packed math ----------------
__device__ __forceinline__ ull pack2(float lo, float hi) {
    ull r; asm("mov.b64 %0, {%1, %2};" : "=l"(r) : "f"(lo), "f"(hi)); return r;
}
__device__ __forceinline__ ull fma2(ull a, ull b, ull c) {
    ull d; asm("fma.rn.f32x2 %0, %1, %2, %3;" : "=l"(d) : "l"(a), "l"(b), "l"(c)); return d;
}
__device__ __forceinline__ float2 unpack2(ull p) {
    float2 f; asm("mov.b64 {%0, %1}, %2;" : "=f"(f.x), "=f"(f.y) : "l"(p)); return f;
}

// ---------------- degree / norm / CSR build ----------------
__global__ void k_count(const int* __restrict__ dst) {
    int e = blockIdx.x * blockDim.x + threadIdx.x;
    if (e < N_EDGES) atomicAdd(&g_degi[dst[e]], 1);
}
__global__ void k_scan1() {
    __shared__ int s[256];
    int i = blockIdx.x * 256 + threadIdx.x;
    int v = (i < N_NODES) ? g_degi[i] : 0;
    if (i < N_NODES) g_dinv[i] = rsqrtf((float)(v + 1));  // +1 self-loop
    s[threadIdx.x] = v;
    __syncthreads();
    for (int d = 1; d < 256; d <<= 1) {
        int t = (threadIdx.x >= d) ? s[threadIdx.x - d] : 0;
        __syncthreads();
        s[threadIdx.x] += t;
        __syncthreads();
    }
    if (i < N_NODES) g_off[i] = s[threadIdx.x] - v;
    if (threadIdx.x == 255) g_bsum[blockIdx.x] = s[255];
}
__global__ void k_scan2(int nblk) {
    __shared__ int s[256];
    int t = threadIdx.x;
    int v = (t < nblk) ? g_bsum[t] : 0;
    s[t] = v;
    __syncthreads();
    for (int d = 1; d < 256; d <<= 1) {
        int u = (t >= d) ? s[t - d] : 0;
        __syncthreads();
        s[t] += u;
        __syncthreads();
    }
    if (t < nblk) g_bsum[t] = s[t] - v;
}
__global__ void k_scan3() {
    int i = blockIdx.x * blockDim.x + threadIdx.x;
    if (i < N_NODES) {
        int o = g_off[i] + g_bsum[i >> 8];
        g_off[i] = o;
        g_cur[i] = o;
        g_degi[i] = 0;   // reset for the next graph replay (deterministic per call)
    }
    if (i == 0) g_off[N_NODES] = N_EDGES;
}
__global__ void k_fill(const int* __restrict__ src, const int* __restrict__ dst) {
    int e = blockIdx.x * blockDim.x + threadIdx.x;
    if (e < N_EDGES) {
        int p = atomicAdd(&g_cur[dst[e]], 1);
        g_col[p] = src[e];
    }
}

// ---------------- GEMM (R10-exact f32x2 microtile), fp16 output -----------------
template <int K, int N, int RB, int TY>
__global__ void k_gemm(const float* __restrict__ X, const float* __restrict__ W,
                       __half* __restrict__ Y) {
    constexpr int CP = N / 32;
    constexpr int T  = TY * 16;
    __shared__ float xs[RB * 33];
    __shared__ float ws[32 * N];
    const int tid = threadIdx.x;
    const int tx = tid & 15, ty = tid >> 4;
    const long r0 = (long)blockIdx.x * RB;

    ull acc[8][CP];
#pragma unroll
    for (int r = 0; r < 8; r++)
#pragma unroll
        for (int c = 0; c < CP; c++) acc[r][c] = 0ull;

    for (int k0 = 0; k0 < K; k0 += 32) {
        for (int t = tid; t < RB * 8; t += T) {
            int r = t >> 3, q = t & 7;
            long row = r0 + r; if (row >= N_NODES) row = N_NODES - 1;
            float4 v = __ldg((const float4*)(X + row * K + k0) + q);
            float* xp = &xs[r * 33 + q * 4];
            xp[0] = v.x; xp[1] = v.y; xp[2] = v.z; xp[3] = v.w;
        }
        const float4* wsrc = (const float4*)(W + (size_t)k0 * N);
        for (int t = tid; t < 8 * N; t += T)
            ((float4*)ws)[t] = __ldg(wsrc + t);
        __syncthreads();

#pragma unroll 8
        for (int kk = 0; kk < 32; kk++) {
            ull wv[CP];
#pragma unroll
            for (int c = 0; c < CP; c++)
                wv[c] = *(const ull*)&ws[kk * N + 2 * tx + 32 * c];
#pragma unroll
            for (int r = 0; r < 8; r++) {
                float xv = xs[(ty * 8 + r) * 33 + kk];
                ull xx = pack2(xv, xv);
#pragma unroll
                for (int c = 0; c < CP; c++) acc[r][c] = fma2(xx, wv[c], acc[r][c]);
            }
        }
        __syncthreads();
    }

#pragma unroll
    for (int r = 0; r < 8; r++) {
        long row = r0 + ty * 8 + r;
        if (row < N_NODES) {
#pragma unroll
            for (int c = 0; c < CP; c++) {
                float2 f = unpack2(acc[r][c]);
                *(__half2*)&Y[row * N + 2 * tx + 32 * c] = __floats2half2_rn(f.x, f.y);
            }
        }
    }
}

// ---------------- pull aggregation, C=128: fp16 gather, 2-way (R10 exact) --------
__global__ void k_pull128(const __half* __restrict__ hraw, const float* __restrict__ b,
                          float* __restrict__ out) {
    int w = (blockIdx.x * blockDim.x + threadIdx.x) >> 5;
    if (w >= N_NODES) return;
    int lane = threadIdx.x & 31;
    float din = g_dinv[w];
    uint2 hr = __ldg((const uint2*)(hraw + (size_t)w * 128) + lane);
    float2 h0a = __half22float2(*(__half2*)&hr.x);
    float2 h0b = __half22float2(*(__half2*)&hr.y);
    float4 bv = __ldg((const float4*)b + lane);
    float sl = din * din;
    float4 acc, acc2 = make_float4(0.f, 0.f, 0.f, 0.f);
    acc.x = fmaf(h0a.x, sl, bv.x); acc.y = fmaf(h0a.y, sl, bv.y);
    acc.z = fmaf(h0b.x, sl, bv.z); acc.w = fmaf(h0b.y, sl, bv.w);

    int s0 = g_off[w], s1 = g_off[w + 1];
    for (int j0 = s0; j0 < s1; j0 += 32) {
        int jj = j0 + lane;
        int cc = 0; float nd = 0.0f;
        if (jj < s1) { cc = g_col[jj]; nd = g_dinv[cc]; }
        int cnt = min(32, s1 - j0);
        int i = 0;
        for (; i + 2 <= cnt; i += 2) {
            int   sA = __shfl_sync(0xffffffffu, cc, i);
            float nA = __shfl_sync(0xffffffffu, nd, i) * din;
            int   sB = __shfl_sync(0xffffffffu, cc, i + 1);
            float nB = __shfl_sync(0xffffffffu, nd, i + 1) * din;
            uint2 rA = __ldg((const uint2*)(hraw + (size_t)sA * 128) + lane);
            uint2 rB = __ldg((const uint2*)(hraw + (size_t)sB * 128) + lane);
            float2 a0 = __half22float2(*(__half2*)&rA.x);
            float2 a1 = __half22float2(*(__half2*)&rA.y);
            float2 b0 = __half22float2(*(__half2*)&rB.x);
            float2 b1 = __half22float2(*(__half2*)&rB.y);
            acc.x  = fmaf(a0.x, nA, acc.x);  acc.y  = fmaf(a0.y, nA, acc.y);
            acc.z  = fmaf(a1.x, nA, acc.z);  acc.w  = fmaf(a1.y, nA, acc.w);
            acc2.x = fmaf(b0.x, nB, acc2.x); acc2.y = fmaf(b0.y, nB, acc2.y);
            acc2.z = fmaf(b1.x, nB, acc2.z); acc2.w = fmaf(b1.y, nB, acc2.w);
        }
        if (i < cnt) {
            int   sA = __shfl_sync(0xffffffffu, cc, i);
            float nA = __shfl_sync(0xffffffffu, nd, i) * din;
            uint2 rA = __ldg((const uint2*)(hraw + (size_t)sA * 128) + lane);
            float2 a0 = __half22float2(*(__half2*)&rA.x);
            float2 a1 = __half22float2(*(__half2*)&rA.y);
            acc.x = fmaf(a0.x, nA, acc.x); acc.y = fmaf(a0.y, nA, acc.y);
            acc.z = fmaf(a1.x, nA, acc.z); acc.w = fmaf(a1.y, nA, acc.w);
        }
    }
    acc.x = fmaxf(acc.x + acc2.x, 0.0f); acc.y = fmaxf(acc.y + acc2.y, 0.0f);
    acc.z = fmaxf(acc.z + acc2.z, 0.0f); acc.w = fmaxf(acc.w + acc2.w, 0.0f);
    ((float4*)(out + (size_t)w * 128))[lane] = acc;
}

// ---------------- pull aggregation, C=64: fp16 gather, 2-way (R10 exact) ---------
__global__ void k_pull64(const __half* __restrict__ hraw, const float* __restrict__ b,
                         float* __restrict__ out) {
    int w = (blockIdx.x * blockDim.x + threadIdx.x) >> 5;
    if (w >= N_NODES) return;
    int lane = threadIdx.x & 31;
    float din = g_dinv[w];
    unsigned hr = __ldg((const unsigned*)(hraw + (size_t)w * 64) + lane);
    float2 h0 = __half22float2(*(__half2*)&hr);
    float2 bv = __ldg((const float2*)b + lane);
    float sl = din * din;
    float2 acc, acc2 = make_float2(0.f, 0.f);
    acc.x = fmaf(h0.x, sl, bv.x); acc.y = fmaf(h0.y, sl, bv.y);

    int s0 = g_off[w], s1 = g_off[w + 1];
    for (int j0 = s0; j0 < s1; j0 += 32) {
        int jj = j0 + lane;
        int cc = 0; float nd = 0.0f;
        if (jj < s1) { cc = g_col[jj]; nd = g_dinv[cc]; }
        int cnt = min(32, s1 - j0);
        int i = 0;
        for (; i + 2 <= cnt; i += 2) {
            int   sA = __shfl_sync(0xffffffffu, cc, i);
            float nA = __shfl_sync(0xffffffffu, nd, i) * din;
            int   sB = __shfl_sync(0xffffffffu, cc, i + 1);
            float nB = __shfl_sync(0xffffffffu, nd, i + 1) * din;
            unsigned rA = __ldg((const unsigned*)(hraw + (size_t)sA * 64) + lane);
            unsigned rB = __ldg((const unsigned*)(hraw + (size_t)sB * 64) + lane);
            float2 fA = __half22float2(*(__half2*)&rA);
            float2 fB = __half22float2(*(__half2*)&rB);
            acc.x  = fmaf(fA.x, nA, acc.x);  acc.y  = fmaf(fA.y, nA, acc.y);
            acc2.x = fmaf(fB.x, nB, acc2.x); acc2.y = fmaf(fB.y, nB, acc2.y);
        }
        if (i < cnt) {
            int   sA = __shfl_sync(0xffffffffu, cc, i);
            float nA = __shfl_sync(0xffffffffu, nd, i) * din;
            unsigned rA = __ldg((const unsigned*)(hraw + (size_t)sA * 64) + lane);
            float2 fA = __half22float2(*(__half2*)&rA);
            acc.x = fmaf(fA.x, nA, acc.x); acc.y = fmaf(fA.y, nA, acc.y);
        }
    }
    acc.x += acc2.x; acc.y += acc2.y;
    ((float2*)(out + (size_t)w * 64))[lane] = acc;
}

// ---------------- launch: R10 structure (CSR ∥ GEMM1) ----------------------------
extern "C" void kernel_launch(void* const* d_in, const int* in_sizes, int n_in,
                              void* d_out, int out_size) {
    const float* x  = (const float*)d_in[0];
    const int*   ei = (const int*)  d_in[1];
    const float* W1 = (const float*)d_in[2];
    const float* b1 = (const float*)d_in[3];
    const float* W2 = (const float*)d_in[4];
    const float* b2 = (const float*)d_in[5];

    const int* src = ei;
    const int* dst = ei + N_EDGES;

    float* out_h2 = (float*)d_out;                       // [N, 64]
    float* out_h1 = out_h2 + (size_t)N_NODES * OUT_DIM;  // [N, 128]

    void *p_hh, *p_h2h;
    cudaGetSymbolAddress(&p_hh,  g_hh);
    cudaGetSymbolAddress(&p_h2h, g_h2h);
    __half* hhbuf  = (__half*)p_hh;
    __half* h2hbuf = (__half*)p_h2h;

    // lazy stream/event creation (first, non-captured, call only)
    static cudaStream_t s2 = nullptr;
    static cudaEvent_t  evFork = nullptr, evJoin = nullptr;
    if (s2 == nullptr) {
        cudaStreamCreateWithFlags(&s2, cudaStreamNonBlocking);
        cudaEventCreateWithFlags(&evFork, cudaEventDisableTiming);
        cudaEventCreateWithFlags(&evJoin, cudaEventDisableTiming);
    }

    const int TB = 256;
    const int nblk_nodes = (N_NODES + TB - 1) / TB;      // 196
    const int nblk_edges = (N_EDGES + TB - 1) / TB;

    // fork: s2 builds CSR while stream 0 runs GEMM1
    cudaEventRecord(evFork, 0);
    cudaStreamWaitEvent(s2, evFork, 0);

    // --- stream 0: GEMM1 -> fp16 hbuf ---
    k_gemm<IN_DIM, HID_DIM, 128, 16><<<(N_NODES + 127) / 128, 256>>>(x, W1, hhbuf);

    // --- stream s2: degree + CSR build (g_degi zeroed by previous scan3 / load) ---
    k_count<<<nblk_edges, TB, 0, s2>>>(dst);
    k_scan1<<<nblk_nodes, TB, 0, s2>>>();
    k_scan2<<<1,          TB, 0, s2>>>(nblk_nodes);
    k_scan3<<<nblk_nodes, TB, 0, s2>>>();
    k_fill <<<nblk_edges, TB, 0, s2>>>(src, dst);

    // join: stream 0 waits for CSR before the pulls
    cudaEventRecord(evJoin, s2);
    cudaStreamWaitEvent(0, evJoin, 0);

    // --- stream 0: pull1 -> GEMM2 -> pull2 ---
    k_pull128<<<(N_NODES * 32 + TB - 1) / TB, TB>>>(hhbuf, b1, out_h1);
    k_gemm<HID_DIM, OUT_DIM, 128, 16><<<(N_NODES + 127) / 128, 256>>>(out_h1, W2, h2hbuf);
    k_pull64<<<(N_NODES * 32 + TB - 1) / TB, TB>>>(h2hbuf, b2, out_h2);
}